// round 9
// baseline (speedup 1.0000x reference)
#include <cuda_runtime.h>

typedef unsigned long long u64;

// packed f32x2 helpers (sm_100+ PTX; doubles FFMA throughput)
__device__ __forceinline__ u64 pk2(float lo, float hi) {
    u64 r; asm("mov.b64 %0,{%1,%2};" : "=l"(r) : "f"(lo), "f"(hi)); return r;
}
__device__ __forceinline__ u64 fma2(u64 a, u64 b, u64 c) {
    u64 d; asm("fma.rn.f32x2 %0,%1,%2,%3;" : "=l"(d) : "l"(a), "l"(b), "l"(c)); return d;
}
__device__ __forceinline__ float sum2(u64 a) {
    float lo, hi; asm("mov.b64 {%0,%1},%2;" : "=f"(lo), "=f"(hi) : "l"(a)); return lo + hi;
}
__device__ __forceinline__ void unpk2(u64 a, float& lo, float& hi) {
    asm("mov.b64 {%0,%1},%2;" : "=f"(lo), "=f"(hi) : "l"(a));
}
__device__ __forceinline__ unsigned smem_u32(const void* p) {
    unsigned a;
    asm("{ .reg .u64 t; cvta.to.shared.u64 t, %1; cvt.u32.u64 %0, t; }" : "=r"(a) : "l"(p));
    return a;
}
__device__ __forceinline__ void cp_async16(unsigned s, const void* g) {
    asm volatile("cp.async.cg.shared.global [%0], [%1], 16;" :: "r"(s), "l"(g));
}

// Scratch (allocation-free rule: __device__ globals)
__device__ float g_n1[2048 * 8];     // n1[row][k]
__device__ float g_n2T[6 * 2048];    // n2 transposed [k][row]

// ---------------------------------------------------------------------------
// Merged GCN kernel, rebuilt for FMA density (>=4 FMA per LDS):
//   Phase A: t = mean_h(wa) @ x     (4-way K-split, a-tile transposed)
//   Phase B: gcn = relu(t@Ww^T+b)   (t transposed in smem; [32][33] w tiles)
//   Phase C: out = gcn@Wxx^T+b
//   Phase D: n1/n2
// grid = 256 blocks (8 i-rows each), 512 threads = 4 groups x 128 lanes.
// ---------------------------------------------------------------------------
__global__ void __launch_bounds__(512) k_gcn(const float* __restrict__ x,
                                             const float* __restrict__ wa,
                                             const float* __restrict__ Ww,
                                             const float* __restrict__ Wb,
                                             const float* __restrict__ Wx_w,
                                             const float* __restrict__ Wxx,
                                             const float* __restrict__ Wxxb,
                                             float* __restrict__ out) {
    cudaTriggerProgrammaticLaunchCompletion();   // let k_adj start now

    __shared__ __align__(16) float pool[8448];   // x tiles / w tiles / partials
    __shared__ __align__(16) float a_sT[512];    // [g][jj][row]
    __shared__ __align__(16) float t_sT[1024];   // [d][row]
    __shared__ __align__(16) float g_s[1024];    // [row][d]   (for phase D)
    __shared__ __align__(16) float g_sT[1024];   // [d][row]

    int b    = blockIdx.x >> 5;
    int i0   = (blockIdx.x & 31) << 3;
    int tid  = threadIdx.x;
    int g    = tid >> 7;       // K-split group 0..3
    int lane = tid & 127;      // d / output column
    int r0   = blockIdx.x * 8;
    const float inv6 = 1.0f / 6.0f;

    // ================= Phase A: t = mean_h(wa) @ x =================
    // group g owns j in [g*64, g*64+64), chunks of 16 j
    float* x_sg = pool + g * 2048;
    u64 acc2[4];
    #pragma unroll
    for (int p = 0; p < 4; p++) acc2[p] = 0ull;

    for (int c = 0; c < 4; c++) {
        int j0 = g * 64 + c * 16;
        // stage x[b][j0..j0+15][0..127] (16 rows = 2048 floats, coalesced)
        const float4* xs = (const float4*)(x + ((long)b * 256 + j0) * 128);
        float4*       xd = (float4*)x_sg;
        #pragma unroll
        for (int q = 0; q < 4; q++) xd[lane + q * 128] = xs[lane + q * 128];
        // a tile transposed: a_sT[g][jj][row], one entry per lane
        {
            int row = lane >> 4, jj = lane & 15;
            float s = 0.0f;
            #pragma unroll
            for (int h = 0; h < 6; h++)
                s += wa[(((long)(b * 6 + h) * 256) + i0 + row) * 256 + j0 + jj];
            a_sT[g * 128 + jj * 8 + row] = s * inv6;
        }
        __syncthreads();
        #pragma unroll
        for (int jj = 0; jj < 16; jj++) {
            float4 a03 = *(const float4*)&a_sT[g * 128 + jj * 8];      // bcast rows 0-3
            float4 a47 = *(const float4*)&a_sT[g * 128 + jj * 8 + 4];  // bcast rows 4-7
            float  xv  = x_sg[jj * 128 + lane];
            u64    xx  = pk2(xv, xv);
            acc2[0] = fma2(*(const u64*)&a03.x, xx, acc2[0]);
            acc2[1] = fma2(*(const u64*)&a03.z, xx, acc2[1]);
            acc2[2] = fma2(*(const u64*)&a47.x, xx, acc2[2]);
            acc2[3] = fma2(*(const u64*)&a47.z, xx, acc2[3]);
        }
        __syncthreads();
    }
    // partials -> pool[g][row][d], reduce over groups into t_sT[d][row]
    #pragma unroll
    for (int p = 0; p < 4; p++) {
        float lo, hi; unpk2(acc2[p], lo, hi);
        pool[g * 1024 + (2 * p) * 128 + lane]     = lo;
        pool[g * 1024 + (2 * p + 1) * 128 + lane] = hi;
    }
    __syncthreads();
    #pragma unroll
    for (int idx = tid; idx < 1024; idx += 512) {
        int row = idx >> 7, d = idx & 127;
        float s = pool[idx] + pool[1024 + idx] + pool[2048 + idx] + pool[3072 + idx];
        t_sT[d * 8 + row] = s;
    }
    __syncthreads();

    // ================= Phase B: gcn = relu(t @ Ww^T + b) =================
    // w staged as 4 x [32][33] transpose tiles; group g handles kk = g*8..g*8+7
    #pragma unroll
    for (int p = 0; p < 4; p++) acc2[p] = 0ull;
    for (int kt = 0; kt < 4; kt++) {
        #pragma unroll
        for (int idx = tid; idx < 4096; idx += 512) {
            int tile = idx >> 10, r = (idx >> 5) & 31, cc = idx & 31;
            pool[tile * 1056 + r * 33 + cc] = Ww[(tile * 32 + r) * 128 + kt * 32 + cc];
        }
        __syncthreads();
        int wbase = (lane >> 5) * 1056 + (lane & 31) * 33;
        #pragma unroll
        for (int k8 = 0; k8 < 8; k8++) {
            int kk = g * 8 + k8;
            float4 t03 = *(const float4*)&t_sT[(kt * 32 + kk) * 8];
            float4 t47 = *(const float4*)&t_sT[(kt * 32 + kk) * 8 + 4];
            float  wv  = pool[wbase + kk];
            u64    ww  = pk2(wv, wv);
            acc2[0] = fma2(*(const u64*)&t03.x, ww, acc2[0]);
            acc2[1] = fma2(*(const u64*)&t03.z, ww, acc2[1]);
            acc2[2] = fma2(*(const u64*)&t47.x, ww, acc2[2]);
            ac2_b:
            acc2[3] = fma2(*(const u64*)&t47.z, ww, acc2[3]);
        }
        __syncthreads();
    }
    #pragma unroll
    for (int p = 0; p < 4; p++) {
        float lo, hi; unpk2(acc2[p], lo, hi);
        pool[g * 1024 + (2 * p) * 128 + lane]     = lo;
        pool[g * 1024 + (2 * p + 1) * 128 + lane] = hi;
    }
    __syncthreads();
    #pragma unroll
    for (int idx = tid; idx < 1024; idx += 512) {
        int row = idx >> 7, d = idx & 127;
        float s = pool[idx] + pool[1024 + idx] + pool[2048 + idx] + pool[3072 + idx];
        s = fmaxf(s + Wb[d], 0.0f);
        g_s[idx]         = s;
        g_sT[d * 8 + row] = s;
    }
    __syncthreads();

    // ================= Phase C: out = gcn @ Wxx^T + b =================
    #pragma unroll
    for (int p = 0; p < 4; p++) acc2[p] = 0ull;
    for (int kt = 0; kt < 4; kt++) {
        #pragma unroll
        for (int idx = tid; idx < 4096; idx += 512) {
            int tile = idx >> 10, r = (idx >> 5) & 31, cc = idx & 31;
            pool[tile * 1056 + r * 33 + cc] = Wxx[(tile * 32 + r) * 128 + kt * 32 + cc];
        }
        __syncthreads();
        int wbase = (lane >> 5) * 1056 + (lane & 31) * 33;
        #pragma unroll
        for (int k8 = 0; k8 < 8; k8++) {
            int kk = g * 8 + k8;
            float4 t03 = *(const float4*)&g_sT[(kt * 32 + kk) * 8];
            float4 t47 = *(const float4*)&g_sT[(kt * 32 + kk) * 8 + 4];
            float  wv  = pool[wbase + kk];
            u64    ww  = pk2(wv, wv);
            acc2[0] = fma2(*(const u64*)&t03.x, ww, acc2[0]);
            acc2[1] = fma2(*(const u64*)&t03.z, ww, acc2[1]);
            acc2[2] = fma2(*(const u64*)&t47.x, ww, acc2[2]);
            acc2[3] = fma2(*(const u64*)&t47.z, ww, acc2[3]);
        }
        __syncthreads();
    }
    #pragma unroll
    for (int p = 0; p < 4; p++) {
        float lo, hi; unpk2(acc2[p], lo, hi);
        pool[g * 1024 + (2 * p) * 128 + lane]     = lo;
        pool[g * 1024 + (2 * p + 1) * 128 + lane] = hi;
    }
    __syncthreads();
    #pragma unroll
    for (int idx = tid; idx < 1024; idx += 512) {
        int row = idx >> 7, d = idx & 127;
        float s = pool[idx] + pool[1024 + idx] + pool[2048 + idx] + pool[3072 + idx];
        out[(long)(r0 + row) * 128 + d] = s + Wxxb[d];
    }

    // ================= Phase D: n1/n2 — 96 dots of length 128 =================
    if (tid < 96) {
        int sel = tid >= 48;                // 0 -> n1, 1 -> n2
        int q   = tid - sel * 48;
        int r   = q / 6, k = q % 6;
        const float* gp = &g_s[r * 128];
        const float* w  = Wx_w + k * 294 + 6 + sel * 128;
        u64 s = 0ull;
        #pragma unroll 8
        for (int d = 0; d < 128; d += 2)
            s = fma2(*(const u64*)&gp[d], pk2(__ldg(&w[d]), __ldg(&w[d + 1])), s);
        float v = sum2(s);
        if (sel == 0) g_n1[(r0 + r) * 8 + k]   = v;
        else          g_n2T[k * 2048 + r0 + r] = v;
    }
}

// ---------------------------------------------------------------------------
// Partial: adj_out[b,k,i,j] = sum_h wa[b,h,i,j]*Wa[k,h]
//                           + sum_e e[b,i,j,e]*We[k,e] + Wx_b[k]
// e tile in chunk-major layout [q][j][4]: conflict-free, ZERO padding -> 33KB
// smem -> 6 blocks/SM. No dependency on k_gcn; overlaps fully via PDL.
// ---------------------------------------------------------------------------
__global__ void __launch_bounds__(256, 6) k_adj(const float* __restrict__ wa,
                                                const float* __restrict__ e,
                                                const float* __restrict__ Wx_w,
                                                const float* __restrict__ Wx_b,
                                                float* __restrict__ adj_out) {
    __shared__ __align__(16) float e_s[8192];      // [q][j][4]
    __shared__ __align__(16) float Wa_s[40];       // [k*6+h]
    __shared__ __align__(16) float We_s[200];      // [k*32+ee]
    __shared__ __align__(16) float bias_s[8];
    int b   = blockIdx.x >> 8;
    int i   = blockIdx.x & 255;
    int tid = threadIdx.x;

    // async-stage e[b,i,:,:] (32KB contiguous): 8 x cp.async.cg per thread
    const float4* e4 = (const float4*)(e + (((long)b * 256 + i) * 256) * 32);
    #pragma unroll
    for (int it = 0; it < 8; it++) {
        int idx = tid + it * 256;
        unsigned dst = smem_u32(&e_s[(idx & 7) * 1024 + (idx >> 3) * 4]);
        cp_async16(dst, &e4[idx]);
    }
    asm volatile("cp.async.commit_group;" ::: "memory");

    // overlap: scalar input loads while the bulk copy is in flight
    float wv[6];
    #pragma unroll
    for (int h = 0; h < 6; h++)
        wv[h] = wa[(((long)(b * 6 + h) * 256) + i) * 256 + tid];
    if (tid < 36) Wa_s[tid] = Wx_w[(tid / 6) * 294 + tid % 6];
    if (tid >= 64 && tid < 256) {
        int t = tid - 64;
        We_s[t] = Wx_w[(t >> 5) * 294 + 262 + (t & 31)];
    }
    if (tid >= 48 && tid < 54) bias_s[tid - 48] = Wx_b[tid - 48];

    asm volatile("cp.async.wait_group 0;" ::: "memory");
    __syncthreads();

    u64 acc2[6];
    #pragma unroll
    for (int k = 0; k < 6; k++) acc2[k] = 0ull;

    // adj term: 3 packed h-pairs x 6 k
    u64 wp0 = pk2(wv[0], wv[1]), wp1 = pk2(wv[2], wv[3]), wp2 = pk2(wv[4], wv[5]);
    #pragma unroll
    for (int k = 0; k < 6; k++) {
        acc2[k] = fma2(*(const u64*)&Wa_s[k * 6 + 0], wp0, acc2[k]);
        acc2[k] = fma2(*(const u64*)&Wa_s[k * 6 + 2], wp1, acc2[k]);
        acc2[k] = fma2(*(const u64*)&Wa_s[k * 6 + 4], wp2, acc2[k]);
    }

    // e term: 8 x LDS.128 (conflict-free, contiguous per chunk)
    #pragma unroll
    for (int q = 0; q < 8; q++) {
        float4 w = *(const float4*)&e_s[q * 1024 + tid * 4];
        u64 ev0 = pk2(w.x, w.y);
        u64 ev1 = pk2(w.z, w.w);
        #pragma unroll
        for (int k = 0; k < 6; k++) {
            acc2[k] = fma2(ev0, *(const u64*)&We_s[k * 32 + q * 4 + 0], acc2[k]);
            acc2[k] = fma2(ev1, *(const u64*)&We_s[k * 32 + q * 4 + 2], acc2[k]);
        }
    }

    long ob = ((long)(b * 6) * 65536) + (long)i * 256 + tid;
    #pragma unroll
    for (int k = 0; k < 6; k++)
        adj_out[ob + (long)k * 65536] = sum2(acc2[k]) + bias_s[k];
}

// ---------------------------------------------------------------------------
// adj_out[b,k,i,j] += n1[b,i,k] + n2[b,j,k]   (streaming float4 RMW)
// grid = B*6*64 = 3072 blocks, 256 threads; block = (b,k, 4 i-rows)
// ---------------------------------------------------------------------------
__global__ void __launch_bounds__(256) k_add(float* __restrict__ adj_out) {
    int bid = blockIdx.x;
    int bk  = bid >> 6;               // b*6+k
    int iq  = bid & 63;
    int b   = bk / 6, k = bk - b * 6;
    int tid = threadIdx.x;
    int ir  = tid >> 6;               // 0..3
    int jj  = (tid & 63) << 2;
    int i   = iq * 4 + ir;

    float  n1v = g_n1[((b * 256 + i) * 8) + k];
    float4 n2v = *(const float4*)&g_n2T[k * 2048 + b * 256 + jj];

    long off = ((long)(b * 6 + k) << 16) + i * 256 + jj;
    float4 v = *(float4*)&adj_out[off];
    v.x += n1v + n2v.x;
    v.y += n1v + n2v.y;
    v.z += n1v + n2v.z;
    v.w += n1v + n2v.w;
    *(float4*)&adj_out[off] = v;
}

// ---------------------------------------------------------------------------
extern "C" void kernel_launch(void* const* d_in, const int* in_sizes, int n_in,
                              void* d_out, int out_size) {
    const float* x     = (const float*)d_in[0];
    const float* wa    = (const float*)d_in[1];
    const float* e     = (const float*)d_in[2];
    const float* W_w   = (const float*)d_in[3];
    const float* W_b   = (const float*)d_in[4];
    const float* Wx_w  = (const float*)d_in[5];
    const float* Wx_b  = (const float*)d_in[6];
    const float* Wxx_w = (const float*)d_in[7];
    const float* Wxx_b = (const float*)d_in[8];

    float* out     = (float*)d_out;            // (B,L,D) = 262144 floats
    float* adj_out = out + 8 * 256 * 128;      // (B,H,L,L) = 3145728 floats

    k_gcn<<<256, 512>>>(x, wa, W_w, W_b, Wx_w, Wxx_w, Wxx_b, out);

    // k_adj overlaps fully with k_gcn (no data dependency, no wait inside)
    cudaLaunchConfig_t cfg = {};
    cfg.gridDim  = dim3(2048);
    cfg.blockDim = dim3(256);
    cudaLaunchAttribute attr[1];
    attr[0].id = cudaLaunchAttributeProgrammaticStreamSerialization;
    attr[0].val.programmaticStreamSerializationAllowed = 1;
    cfg.attrs    = attr;
    cfg.numAttrs = 1;
    cudaLaunchKernelEx(&cfg, k_adj, wa, e, Wx_w, Wx_b, adj_out);

    // waits for both (stream order), folds n1/n2 into adj_out
    k_add<<<3072, 256>>>(adj_out);
}

// round 10
// speedup vs baseline: 1.2058x; 1.2058x over previous
#include <cuda_runtime.h>

typedef unsigned long long u64;

__device__ __forceinline__ u64 pk2(float lo, float hi) {
    u64 r; asm("mov.b64 %0,{%1,%2};" : "=l"(r) : "f"(lo), "f"(hi)); return r;
}
__device__ __forceinline__ u64 fma2(u64 a, u64 b, u64 c) {
    u64 d; asm("fma.rn.f32x2 %0,%1,%2,%3;" : "=l"(d) : "l"(a), "l"(b), "l"(c)); return d;
}
__device__ __forceinline__ float sum2(u64 a) {
    float lo, hi; asm("mov.b64 {%0,%1},%2;" : "=f"(lo), "=f"(hi) : "l"(a)); return lo + hi;
}
__device__ __forceinline__ unsigned smem_u32(const void* p) {
    unsigned a;
    asm("{ .reg .u64 t; cvta.to.shared.u64 t, %1; cvt.u32.u64 %0, t; }" : "=r"(a) : "l"(p));
    return a;
}
__device__ __forceinline__ void cp_async16(unsigned s, const void* g) {
    asm volatile("cp.async.cg.shared.global [%0], [%1], 16;" :: "r"(s), "l"(g));
}

// Scratch
__device__ float g_n1[2048 * 8];     // n1[row][k]
__device__ float g_n2T[6 * 2048];    // n2 transposed [k][row]

// ---------------------------------------------------------------------------
// k_gcn: 256 blocks x 1024 threads (8 groups x 128 lanes).
//   Phase A: t = mean_h(wa) @ x      (8-way j-split)
//   Phase B: gcn = relu(t@Ww^T+b)    (8-way k-split, [32][33] weight tiles)
//   Phase C: out = gcn@Wxx^T+b
//   Phase D: n1/n2
// All inner loops: 2 bcast LDS.128 + 1 LDS.32 per 4 fma2.
// ---------------------------------------------------------------------------
__global__ void __launch_bounds__(1024) k_gcn(const float* __restrict__ x,
                                              const float* __restrict__ wa,
                                              const float* __restrict__ Ww,
                                              const float* __restrict__ Wb,
                                              const float* __restrict__ Wx_w,
                                              const float* __restrict__ Wxx,
                                              const float* __restrict__ Wxxb,
                                              float* __restrict__ out) {
    cudaTriggerProgrammaticLaunchCompletion();

    __shared__ __align__(16) float pool[8448];   // x chunks / w tiles / partials
    __shared__ __align__(16) float a_sT[512];    // [g][jj][row], stride 8
    __shared__ __align__(16) float t_sT[1536];   // [k][row], stride 12 (16B-aligned)
    __shared__ __align__(16) float g_sT[1536];   // [d][row], stride 12

    int b    = blockIdx.x >> 5;
    int i0   = (blockIdx.x & 31) << 3;
    int tid  = threadIdx.x;
    int g    = tid >> 7;       // group 0..7
    int lane = tid & 127;      // d / output column
    int r0   = blockIdx.x * 8;
    const float inv6 = 1.0f / 6.0f;

    // ================= Phase A: t = mean_h(wa) @ x =================
    // group g owns j in [g*32, g*32+32), 4 chunks of 8 j
    float* x_sg = pool + g * 1024;
    u64 acc2[4];
    #pragma unroll
    for (int p = 0; p < 4; p++) acc2[p] = 0ull;

    for (int c = 0; c < 4; c++) {
        int j0 = g * 32 + c * 8;
        const float4* xs = (const float4*)(x + ((long)b * 256 + j0) * 128);
        float4*       xd = (float4*)x_sg;
        xd[lane]       = xs[lane];
        xd[lane + 128] = xs[lane + 128];
        if (lane < 64) {   // a tile: 8 j x 8 rows, transposed
            int jj = lane >> 3, row = lane & 7;
            float s = 0.0f;
            #pragma unroll
            for (int h = 0; h < 6; h++)
                s += wa[(((long)(b * 6 + h) * 256) + i0 + row) * 256 + j0 + jj];
            a_sT[g * 64 + jj * 8 + row] = s * inv6;
        }
        __syncthreads();
        #pragma unroll
        for (int jj = 0; jj < 8; jj++) {
            float4 a03 = *(const float4*)&a_sT[g * 64 + jj * 8];      // bcast, 1 wf
            float4 a47 = *(const float4*)&a_sT[g * 64 + jj * 8 + 4];  // bcast, 1 wf
            float  xv  = x_sg[jj * 128 + lane];
            u64    xx  = pk2(xv, xv);
            acc2[0] = fma2(*(const u64*)&a03.x, xx, acc2[0]);
            acc2[1] = fma2(*(const u64*)&a03.z, xx, acc2[1]);
            acc2[2] = fma2(*(const u64*)&a47.x, xx, acc2[2]);
            acc2[3] = fma2(*(const u64*)&a47.z, xx, acc2[3]);
        }
        __syncthreads();
    }
    // partials: pool[g][p][lane-pair] (u64 stores), then reduce 8 -> t_sT
    #pragma unroll
    for (int p = 0; p < 4; p++)
        *(u64*)&pool[g * 1024 + p * 256 + lane * 2] = acc2[p];
    __syncthreads();
    {
        int row = tid >> 7, d = tid & 127;
        float s = 0.0f;
        #pragma unroll
        for (int q = 0; q < 8; q++)
            s += pool[q * 1024 + (row >> 1) * 256 + d * 2 + (row & 1)];
        t_sT[d * 12 + row] = s;
    }
    __syncthreads();

    // ================= Phase B: gcn = relu(t @ Ww^T + b) =================
    #pragma unroll
    for (int p = 0; p < 4; p++) acc2[p] = 0ull;
    for (int kt = 0; kt < 4; kt++) {
        #pragma unroll
        for (int q = 0; q < 4; q++) {   // stage [32][33] x 4 subtiles
            pool[q * 1056 + (tid >> 5) * 33 + (tid & 31)] =
                Ww[(q * 32 + (tid >> 5)) * 128 + kt * 32 + (tid & 31)];
        }
        __syncthreads();
        int wbase = (lane >> 5) * 1056 + (lane & 31) * 33;
        #pragma unroll
        for (int k4 = 0; k4 < 4; k4++) {
            int kk   = g * 4 + k4;
            int kabs = kt * 32 + kk;
            float4 t03 = *(const float4*)&t_sT[kabs * 12];      // bcast
            float4 t47 = *(const float4*)&t_sT[kabs * 12 + 4];  // bcast
            float  wv  = pool[wbase + kk];
            u64    ww  = pk2(wv, wv);
            acc2[0] = fma2(*(const u64*)&t03.x, ww, acc2[0]);
            acc2[1] = fma2(*(const u64*)&t03.z, ww, acc2[1]);
            acc2[2] = fma2(*(const u64*)&t47.x, ww, acc2[2]);
            acc2[3] = fma2(*(const u64*)&t47.z, ww, acc2[3]);
        }
        __syncthreads();
    }
    #pragma unroll
    for (int p = 0; p < 4; p++)
        *(u64*)&pool[g * 1024 + p * 256 + lane * 2] = acc2[p];
    __syncthreads();
    {
        int row = tid >> 7, d = tid & 127;
        float s = 0.0f;
        #pragma unroll
        for (int q = 0; q < 8; q++)
            s += pool[q * 1024 + (row >> 1) * 256 + d * 2 + (row & 1)];
        g_sT[d * 12 + row] = fmaxf(s + Wb[d], 0.0f);
    }
    __syncthreads();

    // ================= Phase C: out = gcn @ Wxx^T + b =================
    #pragma unroll
    for (int p = 0; p < 4; p++) acc2[p] = 0ull;
    for (int kt = 0; kt < 4; kt++) {
        #pragma unroll
        for (int q = 0; q < 4; q++) {
            pool[q * 1056 + (tid >> 5) * 33 + (tid & 31)] =
                Wxx[(q * 32 + (tid >> 5)) * 128 + kt * 32 + (tid & 31)];
        }
        __syncthreads();
        int wbase = (lane >> 5) * 1056 + (lane & 31) * 33;
        #pragma unroll
        for (int k4 = 0; k4 < 4; k4++) {
            int kk   = g * 4 + k4;
            int kabs = kt * 32 + kk;
            float4 t03 = *(const float4*)&g_sT[kabs * 12];
            float4 t47 = *(const float4*)&g_sT[kabs * 12 + 4];
            float  wv  = pool[wbase + kk];
            u64    ww  = pk2(wv, wv);
            acc2[0] = fma2(*(const u64*)&t03.x, ww, acc2[0]);
            acc2[1] = fma2(*(const u64*)&t03.z, ww, acc2[1]);
            acc2[2] = fma2(*(const u64*)&t47.x, ww, acc2[2]);
            acc2[3] = fma2(*(const u64*)&t47.z, ww, acc2[3]);
        }
        __syncthreads();
    }
    #pragma unroll
    for (int p = 0; p < 4; p++)
        *(u64*)&pool[g * 1024 + p * 256 + lane * 2] = acc2[p];
    __syncthreads();
    {
        int row = tid >> 7, d = tid & 127;
        float s = 0.0f;
        #pragma unroll
        for (int q = 0; q < 8; q++)
            s += pool[q * 1024 + (row >> 1) * 256 + d * 2 + (row & 1)];
        out[(long)(r0 + row) * 128 + d] = s + Wxxb[d];
    }

    // ================= Phase D: n1/n2 — 96 dots of length 128 =================
    if (tid < 96) {
        int sel = tid >= 48;
        int q   = tid - sel * 48;
        int r   = q / 6, k = q % 6;
        const float* w = Wx_w + k * 294 + 6 + sel * 128;
        float s = 0.0f;
        #pragma unroll 8
        for (int d = 0; d < 128; d++)
            s += g_sT[d * 12 + r] * __ldg(&w[d]);
        if (sel == 0) g_n1[(r0 + r) * 8 + k]   = s;
        else          g_n2T[k * 2048 + r0 + r] = s;
    }
}

// ---------------------------------------------------------------------------
// k_adj (r6-proven version): heavy phase independent of k_gcn, n1/n2 folded
// after cudaGridDependencySynchronize(). [j][36] e-layout: conflict-free on
// both cp.async stores and float4 reads.
// ---------------------------------------------------------------------------
__global__ void __launch_bounds__(256, 6) k_adj(const float* __restrict__ wa,
                                                const float* __restrict__ e,
                                                const float* __restrict__ Wx_w,
                                                const float* __restrict__ Wx_b,
                                                float* __restrict__ adj_out) {
    __shared__ __align__(16) float e_s[256 * 36];
    __shared__ __align__(16) float Wa_s[40];
    __shared__ __align__(16) float We_s[200];
    __shared__ __align__(16) float n1b_s[16];
    int b   = blockIdx.x >> 8;
    int i   = blockIdx.x & 255;
    int tid = threadIdx.x;

    const float4* e4 = (const float4*)(e + (((long)b * 256 + i) * 256) * 32);
    #pragma unroll
    for (int it = 0; it < 8; it++) {
        int idx = tid + it * 256;
        unsigned dst = smem_u32(&e_s[(idx >> 3) * 36 + (idx & 7) * 4]);
        cp_async16(dst, &e4[idx]);
    }
    asm volatile("cp.async.commit_group;" ::: "memory");

    float wv[6];
    #pragma unroll
    for (int h = 0; h < 6; h++)
        wv[h] = wa[(((long)(b * 6 + h) * 256) + i) * 256 + tid];
    if (tid < 36) Wa_s[tid] = Wx_w[(tid / 6) * 294 + tid % 6];
    if (tid >= 64 && tid < 256) {
        int t = tid - 64;
        We_s[t] = Wx_w[(t >> 5) * 294 + 262 + (t & 31)];
    }
    if (tid >= 48 && tid < 54) n1b_s[8 + tid - 48] = Wx_b[tid - 48];

    asm volatile("cp.async.wait_group 0;" ::: "memory");
    __syncthreads();

    u64 acc2[6];
    #pragma unroll
    for (int k = 0; k < 6; k++) acc2[k] = 0ull;

    u64 wp0 = pk2(wv[0], wv[1]), wp1 = pk2(wv[2], wv[3]), wp2 = pk2(wv[4], wv[5]);
    #pragma unroll
    for (int k = 0; k < 6; k++) {
        acc2[k] = fma2(*(const u64*)&Wa_s[k * 6 + 0], wp0, acc2[k]);
        acc2[k] = fma2(*(const u64*)&Wa_s[k * 6 + 2], wp1, acc2[k]);
        acc2[k] = fma2(*(const u64*)&Wa_s[k * 6 + 4], wp2, acc2[k]);
    }

    const float4* ep = (const float4*)&e_s[tid * 36];
    #pragma unroll
    for (int q = 0; q < 8; q++) {
        float4 w = ep[q];
        u64 ev0 = pk2(w.x, w.y);
        u64 ev1 = pk2(w.z, w.w);
        #pragma unroll
        for (int k = 0; k < 6; k++) {
            acc2[k] = fma2(ev0, *(const u64*)&We_s[k * 32 + q * 4 + 0], acc2[k]);
            acc2[k] = fma2(ev1, *(const u64*)&We_s[k * 32 + q * 4 + 2], acc2[k]);
        }
    }

    cudaGridDependencySynchronize();

    if (tid < 6) n1b_s[tid] = g_n1[((long)b * 256 + i) * 8 + tid];
    float n2v[6];
    #pragma unroll
    for (int k = 0; k < 6; k++) n2v[k] = g_n2T[k * 2048 + b * 256 + tid];
    __syncthreads();

    long ob = ((long)(b * 6) * 65536) + (long)i * 256 + tid;
    #pragma unroll
    for (int k = 0; k < 6; k++)
        adj_out[ob + (long)k * 65536] = sum2(acc2[k]) + n1b_s[k] + n1b_s[8 + k] + n2v[k];
}

// ---------------------------------------------------------------------------
extern "C" void kernel_launch(void* const* d_in, const int* in_sizes, int n_in,
                              void* d_out, int out_size) {
    const float* x     = (const float*)d_in[0];
    const float* wa    = (const float*)d_in[1];
    const float* e     = (const float*)d_in[2];
    const float* W_w   = (const float*)d_in[3];
    const float* W_b   = (const float*)d_in[4];
    const float* Wx_w  = (const float*)d_in[5];
    const float* Wx_b  = (const float*)d_in[6];
    const float* Wxx_w = (const float*)d_in[7];
    const float* Wxx_b = (const float*)d_in[8];

    float* out     = (float*)d_out;            // (B,L,D)
    float* adj_out = out + 8 * 256 * 128;      // (B,H,L,L)

    k_gcn<<<256, 1024>>>(x, wa, W_w, W_b, Wx_w, Wxx_w, Wxx_b, out);

    cudaLaunchConfig_t cfg = {};
    cfg.gridDim  = dim3(2048);
    cfg.blockDim = dim3(256);
    cudaLaunchAttribute attr[1];
    attr[0].id = cudaLaunchAttributeProgrammaticStreamSerialization;
    attr[0].val.programmaticStreamSerializationAllowed = 1;
    cfg.attrs    = attr;
    cfg.numAttrs = 1;
    cudaLaunchKernelEx(&cfg, k_adj, wa, e, Wx_w, Wx_b, adj_out);
}